// round 2
// baseline (speedup 1.0000x reference)
#include <cuda_runtime.h>
#include <cstdint>

// Problem constants
#define BV  8
#define CV  32    // input channels
#define RV  32    // recurrent channels
#define TV  32
#define HV  64
#define WV  64
#define HWV 4096  // 64*64

// Derived
#define FRAME  (BV*RV*HWV)          // 1,048,576 elems (one h-state)
#define SEQBUF (TV*BV*RV*HWV)       // 33,554,432 elems per gate buffer
#define WSZ    9216                 // 32*32*3*3 weights per conv

// ---------------------------------------------------------------------------
// Device scratch (allocation-free rule: static __device__ globals)
// ---------------------------------------------------------------------------
__device__ float g_Wt[6 * WSZ];     // transposed weights [slot][cin][ky][kx][cout]
__device__ float g_UI[SEQBUF];      // precomputed input-conv for update gate
__device__ float g_RI[SEQBUF];      // ... reset gate
__device__ float g_OI[SEQBUF];      // ... out gate
__device__ float g_H [FRAME];       // hidden state
__device__ float g_U [FRAME];       // update gate values (per step)
__device__ float g_HR[FRAME];       // h * reset (per step)

// Weight slots in g_Wt: 0=ui 1=ri 2=oi 3=uh 4=rh 5=oh

__device__ __forceinline__ float fast_sigmoid(float x) {
    float e = __expf(-x);
    return __fdividef(1.0f, 1.0f + e);
}
__device__ __forceinline__ float fast_tanh(float x) {
    float e = __expf(-2.0f * x);
    return __fdividef(1.0f - e, 1.0f + e);
}

// ---------------------------------------------------------------------------
// Weight transpose:  OIHW [cout][cin][ky][kx]  ->  [cin][ky][kx][cout]
// ---------------------------------------------------------------------------
__global__ void wtrans_kernel(const float* __restrict__ w_ui, const float* __restrict__ w_ri,
                              const float* __restrict__ w_oi, const float* __restrict__ w_uh,
                              const float* __restrict__ w_rh, const float* __restrict__ w_oh) {
    int slot = blockIdx.x;
    const float* src;
    switch (slot) {
        case 0: src = w_ui; break;
        case 1: src = w_ri; break;
        case 2: src = w_oi; break;
        case 3: src = w_uh; break;
        case 4: src = w_rh; break;
        default: src = w_oh; break;
    }
    float* dst = g_Wt + slot * WSZ;
    for (int i = threadIdx.x; i < WSZ; i += blockDim.x) {
        int cout = i & 31;
        int k    = (i >> 5) % 9;
        int cin  = i / 288;
        dst[i] = src[(cout * 32 + cin) * 9 + k];
    }
}

__global__ void zeroH_kernel() {
    for (int i = blockIdx.x * blockDim.x + threadIdx.x; i < FRAME; i += gridDim.x * blockDim.x)
        g_H[i] = 0.0f;
}

// ---------------------------------------------------------------------------
// Precompute input convs: for each (b,t) frame, conv3x3 pad1, Cin=32 -> Cout=32,
// one of 3 weight sets selected by blockIdx.z. Output layout:
//   G[((t*B + b)*32 + c)*4096 + y*64 + x]
// Tile: 4 rows x 64 cols x 32 couts per block. 256 threads.
// smem: in 6*66*32 + w 9216 + bias 32 = 21920 floats = 87680 B
// ---------------------------------------------------------------------------
#define SMEM_PC ((6*66*32 + WSZ + 32) * 4)

__global__ void __launch_bounds__(256, 2)
conv_in_kernel(const float* __restrict__ x,
               const float* __restrict__ b_ui, const float* __restrict__ b_ri,
               const float* __restrict__ b_oi) {
    extern __shared__ float smem[];
    float* sIn = smem;               // 6*66*32 = 12672
    float* sW  = smem + 12672;       // 9216
    float* sB  = sW + WSZ;           // 32

    const int j   = blockIdx.z;          // 0=ui 1=ri 2=oi
    const int f   = blockIdx.y;          // b*T + t
    const int b   = f >> 5;
    const int t   = f & 31;
    const int y0  = blockIdx.x * 4;
    const int tid = threadIdx.x;

    const float* gw = g_Wt + j * WSZ;
    for (int i = tid; i < WSZ; i += 256) sW[i] = gw[i];
    if (tid < 32) sB[tid] = (j == 0 ? b_ui : j == 1 ? b_ri : b_oi)[tid];

    // x[b][c][t][y][x]: base for this (b,t)
    const float* xb = x + ((size_t)b * CV * TV + t) * HWV;
    for (int i = tid; i < 6 * 66 * 32; i += 256) {
        int cin = i / 396;
        int rem = i - cin * 396;
        int rr  = rem / 66;
        int cc  = rem - rr * 66;
        int gy  = y0 - 1 + rr;
        int gx  = cc - 1;
        float v = 0.0f;
        if ((unsigned)gy < 64u && (unsigned)gx < 64u)
            v = xb[(size_t)cin * (TV * HWV) + gy * 64 + gx];
        sIn[cin * 396 + rr * 66 + cc] = v;
    }
    __syncthreads();

    const int col = tid & 63;
    const int c0  = (tid >> 6) * 8;

    float acc[4][8];
#pragma unroll
    for (int r = 0; r < 4; ++r)
#pragma unroll
        for (int c = 0; c < 8; ++c) acc[r][c] = 0.0f;

    for (int cin = 0; cin < 32; ++cin) {
        const float* inC = sIn + cin * 396 + col;
        const float* wC  = sW + cin * 288 + c0;
#pragma unroll
        for (int kx = 0; kx < 3; ++kx) {
            float iv[6];
#pragma unroll
            for (int rr = 0; rr < 6; ++rr) iv[rr] = inC[rr * 66 + kx];
#pragma unroll
            for (int ky = 0; ky < 3; ++ky) {
                const float4 w0 = *(const float4*)(wC + (ky * 3 + kx) * 32);
                const float4 w1 = *(const float4*)(wC + (ky * 3 + kx) * 32 + 4);
#pragma unroll
                for (int r = 0; r < 4; ++r) {
                    float v = iv[r + ky];
                    acc[r][0] += v * w0.x; acc[r][1] += v * w0.y;
                    acc[r][2] += v * w0.z; acc[r][3] += v * w0.w;
                    acc[r][4] += v * w1.x; acc[r][5] += v * w1.y;
                    acc[r][6] += v * w1.z; acc[r][7] += v * w1.w;
                }
            }
        }
    }

    float* G = (j == 0) ? g_UI : (j == 1) ? g_RI : g_OI;
    const size_t fbase = ((size_t)t * BV + b) * 32 * 4096;
#pragma unroll
    for (int c = 0; c < 8; ++c) {
        float bias = sB[c0 + c];
#pragma unroll
        for (int r = 0; r < 4; ++r)
            G[fbase + (size_t)(c0 + c) * 4096 + (y0 + r) * 64 + col] = acc[r][c] + bias;
    }
}

// ---------------------------------------------------------------------------
// Phase A (per step t): u = sigmoid(UI[t] + conv_uh(h)), r = sigmoid(RI[t] + conv_rh(h))
// writes g_U = u, g_HR = h * r.  Tile: 2 rows x 64 cols x 32 couts, two convs.
// smem: in 4*66*32 + 2*9216 + 64 = 26944 floats = 107776 B
// ---------------------------------------------------------------------------
#define SMEM_A ((4*66*32 + 2*WSZ + 64) * 4)

__global__ void __launch_bounds__(256, 2)
phaseA_kernel(int t, const float* __restrict__ b_uh, const float* __restrict__ b_rh) {
    extern __shared__ float smem[];
    float* sIn = smem;               // 4*66*32 = 8448
    float* sWu = smem + 8448;        // 9216
    float* sWr = sWu + WSZ;          // 9216
    float* sBu = sWr + WSZ;          // 32
    float* sBr = sBu + 32;           // 32

    const int b   = blockIdx.y;
    const int y0  = blockIdx.x * 2;
    const int tid = threadIdx.x;

    for (int i = tid; i < WSZ; i += 256) {
        sWu[i] = g_Wt[3 * WSZ + i];
        sWr[i] = g_Wt[4 * WSZ + i];
    }
    if (tid < 32) { sBu[tid] = b_uh[tid]; sBr[tid] = b_rh[tid]; }

    const float* hb = g_H + (size_t)b * RV * HWV;
    for (int i = tid; i < 4 * 66 * 32; i += 256) {
        int cin = i / 264;
        int rem = i - cin * 264;
        int rr  = rem / 66;
        int cc  = rem - rr * 66;
        int gy  = y0 - 1 + rr;
        int gx  = cc - 1;
        float v = 0.0f;
        if ((unsigned)gy < 64u && (unsigned)gx < 64u)
            v = hb[cin * HWV + gy * 64 + gx];
        sIn[cin * 264 + rr * 66 + cc] = v;
    }
    __syncthreads();

    const int col = tid & 63;
    const int c0  = (tid >> 6) * 8;

    float aU[2][8], aR[2][8];
#pragma unroll
    for (int r = 0; r < 2; ++r)
#pragma unroll
        for (int c = 0; c < 8; ++c) { aU[r][c] = 0.0f; aR[r][c] = 0.0f; }

    for (int cin = 0; cin < 32; ++cin) {
        const float* inC = sIn + cin * 264 + col;
        const float* wU  = sWu + cin * 288 + c0;
        const float* wR  = sWr + cin * 288 + c0;
#pragma unroll
        for (int kx = 0; kx < 3; ++kx) {
            float iv[4];
#pragma unroll
            for (int rr = 0; rr < 4; ++rr) iv[rr] = inC[rr * 66 + kx];
#pragma unroll
            for (int ky = 0; ky < 3; ++ky) {
                const float4 u0 = *(const float4*)(wU + (ky * 3 + kx) * 32);
                const float4 u1 = *(const float4*)(wU + (ky * 3 + kx) * 32 + 4);
                const float4 r0 = *(const float4*)(wR + (ky * 3 + kx) * 32);
                const float4 r1 = *(const float4*)(wR + (ky * 3 + kx) * 32 + 4);
#pragma unroll
                for (int r = 0; r < 2; ++r) {
                    float v = iv[r + ky];
                    aU[r][0] += v * u0.x; aU[r][1] += v * u0.y;
                    aU[r][2] += v * u0.z; aU[r][3] += v * u0.w;
                    aU[r][4] += v * u1.x; aU[r][5] += v * u1.y;
                    aU[r][6] += v * u1.z; aU[r][7] += v * u1.w;
                    aR[r][0] += v * r0.x; aR[r][1] += v * r0.y;
                    aR[r][2] += v * r0.z; aR[r][3] += v * r0.w;
                    aR[r][4] += v * r1.x; aR[r][5] += v * r1.y;
                    aR[r][6] += v * r1.z; aR[r][7] += v * r1.w;
                }
            }
        }
    }

    const size_t fbase = ((size_t)t * BV + b) * 32 * 4096;
    const float* UIt = g_UI + fbase;
    const float* RIt = g_RI + fbase;
#pragma unroll
    for (int c = 0; c < 8; ++c) {
        int ch = c0 + c;
#pragma unroll
        for (int r = 0; r < 2; ++r) {
            int pix = (y0 + r) * 64 + col;
            int idx = (b * 32 + ch) * 4096 + pix;
            float pu = aU[r][c] + sBu[ch] + UIt[(size_t)ch * 4096 + pix];
            float pr = aR[r][c] + sBr[ch] + RIt[(size_t)ch * 4096 + pix];
            float uval = fast_sigmoid(pu);
            float rval = fast_sigmoid(pr);
            float h = g_H[idx];
            g_U [idx] = uval;
            g_HR[idx] = h * rval;
        }
    }
}

// ---------------------------------------------------------------------------
// Phase B (per step t): cand = tanh(OI[t] + conv_oh(h*r)); h = h + u*(cand - h)
// writes new h and output[b][c][t][pix].
// smem: in 4*66*32 + 9216 + 32 = 17696 floats = 70784 B
// ---------------------------------------------------------------------------
#define SMEM_B ((4*66*32 + WSZ + 32) * 4)

__global__ void __launch_bounds__(256, 2)
phaseB_kernel(int t, const float* __restrict__ b_oh, float* __restrict__ out) {
    extern __shared__ float smem[];
    float* sIn = smem;               // 8448
    float* sW  = smem + 8448;        // 9216
    float* sB  = sW + WSZ;           // 32

    const int b   = blockIdx.y;
    const int y0  = blockIdx.x * 2;
    const int tid = threadIdx.x;

    for (int i = tid; i < WSZ; i += 256) sW[i] = g_Wt[5 * WSZ + i];
    if (tid < 32) sB[tid] = b_oh[tid];

    const float* hb = g_HR + (size_t)b * RV * HWV;
    for (int i = tid; i < 4 * 66 * 32; i += 256) {
        int cin = i / 264;
        int rem = i - cin * 264;
        int rr  = rem / 66;
        int cc  = rem - rr * 66;
        int gy  = y0 - 1 + rr;
        int gx  = cc - 1;
        float v = 0.0f;
        if ((unsigned)gy < 64u && (unsigned)gx < 64u)
            v = hb[cin * HWV + gy * 64 + gx];
        sIn[cin * 264 + rr * 66 + cc] = v;
    }
    __syncthreads();

    const int col = tid & 63;
    const int c0  = (tid >> 6) * 8;

    float acc[2][8];
#pragma unroll
    for (int r = 0; r < 2; ++r)
#pragma unroll
        for (int c = 0; c < 8; ++c) acc[r][c] = 0.0f;

    for (int cin = 0; cin < 32; ++cin) {
        const float* inC = sIn + cin * 264 + col;
        const float* wC  = sW + cin * 288 + c0;
#pragma unroll
        for (int kx = 0; kx < 3; ++kx) {
            float iv[4];
#pragma unroll
            for (int rr = 0; rr < 4; ++rr) iv[rr] = inC[rr * 66 + kx];
#pragma unroll
            for (int ky = 0; ky < 3; ++ky) {
                const float4 w0 = *(const float4*)(wC + (ky * 3 + kx) * 32);
                const float4 w1 = *(const float4*)(wC + (ky * 3 + kx) * 32 + 4);
#pragma unroll
                for (int r = 0; r < 2; ++r) {
                    float v = iv[r + ky];
                    acc[r][0] += v * w0.x; acc[r][1] += v * w0.y;
                    acc[r][2] += v * w0.z; acc[r][3] += v * w0.w;
                    acc[r][4] += v * w1.x; acc[r][5] += v * w1.y;
                    acc[r][6] += v * w1.z; acc[r][7] += v * w1.w;
                }
            }
        }
    }

    const size_t fbase = ((size_t)t * BV + b) * 32 * 4096;
    const float* OIt = g_OI + fbase;
#pragma unroll
    for (int c = 0; c < 8; ++c) {
        int ch = c0 + c;
#pragma unroll
        for (int r = 0; r < 2; ++r) {
            int pix  = (y0 + r) * 64 + col;
            int idx  = (b * 32 + ch) * 4096 + pix;
            float cand = fast_tanh(acc[r][c] + sB[ch] + OIt[(size_t)ch * 4096 + pix]);
            float u = g_U[idx];
            float h = g_H[idx];
            float hn = h + u * (cand - h);
            g_H[idx] = hn;
            out[((size_t)(b * 32 + ch) * TV + t) * HWV + pix] = hn;
        }
    }
}

// ---------------------------------------------------------------------------
// Launch
// ---------------------------------------------------------------------------
extern "C" void kernel_launch(void* const* d_in, const int* in_sizes, int n_in,
                              void* d_out, int out_size) {
    const float* x    = (const float*)d_in[0];
    const float* w_ri = (const float*)d_in[1];
    const float* b_ri = (const float*)d_in[2];
    const float* w_rh = (const float*)d_in[3];
    const float* b_rh = (const float*)d_in[4];
    const float* w_ui = (const float*)d_in[5];
    const float* b_ui = (const float*)d_in[6];
    const float* w_uh = (const float*)d_in[7];
    const float* b_uh = (const float*)d_in[8];
    const float* w_oi = (const float*)d_in[9];
    const float* b_oi = (const float*)d_in[10];
    const float* w_oh = (const float*)d_in[11];
    const float* b_oh = (const float*)d_in[12];
    float* out = (float*)d_out;

    cudaFuncSetAttribute((const void*)conv_in_kernel,
                         cudaFuncAttributeMaxDynamicSharedMemorySize, SMEM_PC);
    cudaFuncSetAttribute((const void*)phaseA_kernel,
                         cudaFuncAttributeMaxDynamicSharedMemorySize, SMEM_A);
    cudaFuncSetAttribute((const void*)phaseB_kernel,
                         cudaFuncAttributeMaxDynamicSharedMemorySize, SMEM_B);

    wtrans_kernel<<<6, 256>>>(w_ui, w_ri, w_oi, w_uh, w_rh, w_oh);
    zeroH_kernel<<<1024, 256>>>();

    // Parallel input convs over all (b,t) frames, 3 weight sets
    conv_in_kernel<<<dim3(16, BV * TV, 3), 256, SMEM_PC>>>(x, b_ui, b_ri, b_oi);

    // Sequential scan over frames
    for (int t = 0; t < TV; ++t) {
        phaseA_kernel<<<dim3(32, BV), 256, SMEM_A>>>(t, b_uh, b_rh);
        phaseB_kernel<<<dim3(32, BV), 256, SMEM_B>>>(t, b_oh, out);
    }
}

// round 4
// speedup vs baseline: 1.1541x; 1.1541x over previous
#include <cuda_runtime.h>
#include <cstdint>

// Problem constants
#define BV  8
#define CV  32
#define RV  32
#define TV  32
#define HV  64
#define WV  64
#define HWV 4096

#define FRAME  (BV*RV*HWV)
#define SEQBUF (TV*BV*RV*HWV)
#define WSZ    9216            // 32*32*3*3

// ---------------------------------------------------------------------------
// Device scratch
// ---------------------------------------------------------------------------
__device__ float g_Wt[6 * WSZ];     // [slot][cin][ky][kx][cout]
__device__ float g_UI[SEQBUF];
__device__ float g_RI[SEQBUF];
__device__ float g_OI[SEQBUF];
__device__ float g_H [FRAME];
__device__ float g_U [FRAME];
__device__ float g_HR[FRAME];

// slots: 0=ui 1=ri 2=oi 3=uh 4=rh 5=oh

typedef unsigned long long u64;

// packed f32x2 helpers (sm_100a)
__device__ __forceinline__ void ffma2(u64& acc, u64 a, u64 b) {
    asm("fma.rn.f32x2 %0, %1, %2, %0;" : "+l"(acc) : "l"(a), "l"(b));
}
__device__ __forceinline__ u64 pack2(float v) {
    u64 r; asm("mov.b64 %0, {%1, %1};" : "=l"(r) : "f"(v)); return r;
}
__device__ __forceinline__ float2 unpack2(u64 v) {
    float2 f; asm("mov.b64 {%0, %1}, %2;" : "=f"(f.x), "=f"(f.y) : "l"(v)); return f;
}

__device__ __forceinline__ float fast_sigmoid(float x) {
    float e = __expf(-x);
    return __fdividef(1.0f, 1.0f + e);
}
__device__ __forceinline__ float fast_tanh(float x) {
    float e = __expf(-2.0f * x);
    return __fdividef(1.0f - e, 1.0f + e);
}

// ---------------------------------------------------------------------------
// Weight transpose: OIHW [cout][cin][ky][kx] -> [cin][ky][kx][cout]
// ---------------------------------------------------------------------------
__global__ void wtrans_kernel(const float* __restrict__ w_ui, const float* __restrict__ w_ri,
                              const float* __restrict__ w_oi, const float* __restrict__ w_uh,
                              const float* __restrict__ w_rh, const float* __restrict__ w_oh) {
    int slot = blockIdx.x;
    const float* src;
    switch (slot) {
        case 0: src = w_ui; break;
        case 1: src = w_ri; break;
        case 2: src = w_oi; break;
        case 3: src = w_uh; break;
        case 4: src = w_rh; break;
        default: src = w_oh; break;
    }
    float* dst = g_Wt + slot * WSZ;
    for (int i = threadIdx.x; i < WSZ; i += blockDim.x) {
        int cout = i & 31;
        int k    = (i >> 5) % 9;
        int cin  = i / 288;
        dst[i] = src[(cout * 32 + cin) * 9 + k];
    }
}

__global__ void zeroH_kernel() {
    for (int i = blockIdx.x * blockDim.x + threadIdx.x; i < FRAME; i += gridDim.x * blockDim.x)
        g_H[i] = 0.0f;
}

// ---------------------------------------------------------------------------
// Input convs (parallel over all (b,t) frames, 3 weight sets).
// Tile: 4 rows x 64 cols x 32 couts, 256 threads, packed f32x2 over cout pairs.
// ---------------------------------------------------------------------------
#define SMEM_PC ((6*66*32 + WSZ + 32) * 4)

__global__ void __launch_bounds__(256, 2)
conv_in_kernel(const float* __restrict__ x,
               const float* __restrict__ b_ui, const float* __restrict__ b_ri,
               const float* __restrict__ b_oi) {
    extern __shared__ float smem[];
    float* sIn = smem;               // 6*66*32 = 12672
    float* sW  = smem + 12672;       // 9216
    float* sB  = sW + WSZ;           // 32

    const int j   = blockIdx.z;
    const int f   = blockIdx.y;
    const int b   = f >> 5;
    const int t   = f & 31;
    const int y0  = blockIdx.x * 4;
    const int tid = threadIdx.x;

    const float* gw = g_Wt + j * WSZ;
    for (int i = tid; i < WSZ; i += 256) sW[i] = gw[i];
    if (tid < 32) sB[tid] = (j == 0 ? b_ui : j == 1 ? b_ri : b_oi)[tid];

    const float* xb = x + ((size_t)b * CV * TV + t) * HWV;
    for (int i = tid; i < 6 * 66 * 32; i += 256) {
        int cin = i / 396;
        int rem = i - cin * 396;
        int rr  = rem / 66;
        int cc  = rem - rr * 66;
        int gy  = y0 - 1 + rr;
        int gx  = cc - 1;
        float v = 0.0f;
        if ((unsigned)gy < 64u && (unsigned)gx < 64u)
            v = xb[(size_t)cin * (TV * HWV) + gy * 64 + gx];
        sIn[cin * 396 + rr * 66 + cc] = v;
    }
    __syncthreads();

    const int col = tid & 63;
    const int c0  = (tid >> 6) * 8;   // 8 couts = 4 f32x2 pairs

    u64 acc[4][4];
#pragma unroll
    for (int r = 0; r < 4; ++r)
#pragma unroll
        for (int p = 0; p < 4; ++p) acc[r][p] = 0ULL;

    for (int cin = 0; cin < 32; ++cin) {
        const float* inC = sIn + cin * 396 + col;
        // base at [cin][0][0][c0]; k-position stride = 32 floats = 8 ulonglong2
        const ulonglong2* wC = (const ulonglong2*)(sW + cin * 288 + c0);
#pragma unroll
        for (int kx = 0; kx < 3; ++kx) {
            u64 vv[6];
#pragma unroll
            for (int rr = 0; rr < 6; ++rr) vv[rr] = pack2(inC[rr * 66 + kx]);
#pragma unroll
            for (int ky = 0; ky < 3; ++ky) {
                ulonglong2 w0 = wC[(ky * 3 + kx) * 8];
                ulonglong2 w1 = wC[(ky * 3 + kx) * 8 + 1];
#pragma unroll
                for (int r = 0; r < 4; ++r) {
                    u64 v = vv[r + ky];
                    ffma2(acc[r][0], v, w0.x);
                    ffma2(acc[r][1], v, w0.y);
                    ffma2(acc[r][2], v, w1.x);
                    ffma2(acc[r][3], v, w1.y);
                }
            }
        }
    }

    float* G = (j == 0) ? g_UI : (j == 1) ? g_RI : g_OI;
    const size_t fbase = ((size_t)t * BV + b) * 32 * 4096;
#pragma unroll
    for (int p = 0; p < 4; ++p) {
        int ch = c0 + 2 * p;
        float b0 = sB[ch], b1 = sB[ch + 1];
#pragma unroll
        for (int r = 0; r < 4; ++r) {
            float2 a = unpack2(acc[r][p]);
            int pix = (y0 + r) * 64 + col;
            G[fbase + (size_t)ch * 4096 + pix]       = a.x + b0;
            G[fbase + (size_t)(ch + 1) * 4096 + pix] = a.y + b1;
        }
    }
}

// ---------------------------------------------------------------------------
// Phase A: u = sigmoid(UI + conv_uh(h)), r = sigmoid(RI + conv_rh(h))
// writes g_U, g_HR. Tile: 2 rows x 64 cols x 32 couts. Packed f32x2.
// ---------------------------------------------------------------------------
#define SMEM_A ((4*66*32 + 2*WSZ + 64) * 4)

__global__ void __launch_bounds__(256, 2)
phaseA_kernel(int t, const float* __restrict__ b_uh, const float* __restrict__ b_rh) {
    extern __shared__ float smem[];
    float* sIn = smem;               // 4*66*32 = 8448
    float* sWu = smem + 8448;        // 9216
    float* sWr = sWu + WSZ;          // 9216
    float* sBu = sWr + WSZ;
    float* sBr = sBu + 32;

    const int b   = blockIdx.y;
    const int y0  = blockIdx.x * 2;
    const int tid = threadIdx.x;

    for (int i = tid; i < WSZ; i += 256) {
        sWu[i] = g_Wt[3 * WSZ + i];
        sWr[i] = g_Wt[4 * WSZ + i];
    }
    if (tid < 32) { sBu[tid] = b_uh[tid]; sBr[tid] = b_rh[tid]; }

    const float* hb = g_H + (size_t)b * RV * HWV;
    for (int i = tid; i < 4 * 66 * 32; i += 256) {
        int cin = i / 264;
        int rem = i - cin * 264;
        int rr  = rem / 66;
        int cc  = rem - rr * 66;
        int gy  = y0 - 1 + rr;
        int gx  = cc - 1;
        float v = 0.0f;
        if ((unsigned)gy < 64u && (unsigned)gx < 64u)
            v = hb[cin * HWV + gy * 64 + gx];
        sIn[cin * 264 + rr * 66 + cc] = v;
    }
    __syncthreads();

    const int col = tid & 63;
    const int c0  = (tid >> 6) * 8;

    u64 aU[2][4], aR[2][4];
#pragma unroll
    for (int r = 0; r < 2; ++r)
#pragma unroll
        for (int p = 0; p < 4; ++p) { aU[r][p] = 0ULL; aR[r][p] = 0ULL; }

    for (int cin = 0; cin < 32; ++cin) {
        const float* inC = sIn + cin * 264 + col;
        const ulonglong2* wU = (const ulonglong2*)(sWu + cin * 288 + c0);
        const ulonglong2* wR = (const ulonglong2*)(sWr + cin * 288 + c0);
#pragma unroll
        for (int kx = 0; kx < 3; ++kx) {
            u64 vv[4];
#pragma unroll
            for (int rr = 0; rr < 4; ++rr) vv[rr] = pack2(inC[rr * 66 + kx]);
#pragma unroll
            for (int ky = 0; ky < 3; ++ky) {
                ulonglong2 u0 = wU[(ky * 3 + kx) * 8];
                ulonglong2 u1 = wU[(ky * 3 + kx) * 8 + 1];
                ulonglong2 r0 = wR[(ky * 3 + kx) * 8];
                ulonglong2 r1 = wR[(ky * 3 + kx) * 8 + 1];
#pragma unroll
                for (int r = 0; r < 2; ++r) {
                    u64 v = vv[r + ky];
                    ffma2(aU[r][0], v, u0.x);
                    ffma2(aU[r][1], v, u0.y);
                    ffma2(aU[r][2], v, u1.x);
                    ffma2(aU[r][3], v, u1.y);
                    ffma2(aR[r][0], v, r0.x);
                    ffma2(aR[r][1], v, r0.y);
                    ffma2(aR[r][2], v, r1.x);
                    ffma2(aR[r][3], v, r1.y);
                }
            }
        }
    }

    const size_t fbase = ((size_t)t * BV + b) * 32 * 4096;
    const float* UIt = g_UI + fbase;
    const float* RIt = g_RI + fbase;
#pragma unroll
    for (int p = 0; p < 4; ++p) {
        int ch = c0 + 2 * p;
        float bu0 = sBu[ch], bu1 = sBu[ch + 1];
        float br0 = sBr[ch], br1 = sBr[ch + 1];
#pragma unroll
        for (int r = 0; r < 2; ++r) {
            float2 au = unpack2(aU[r][p]);
            float2 ar = unpack2(aR[r][p]);
            int pix  = (y0 + r) * 64 + col;
            int idx0 = (b * 32 + ch) * 4096 + pix;
            int idx1 = idx0 + 4096;
            float u0 = fast_sigmoid(au.x + bu0 + UIt[(size_t)ch * 4096 + pix]);
            float u1 = fast_sigmoid(au.y + bu1 + UIt[(size_t)(ch + 1) * 4096 + pix]);
            float r0 = fast_sigmoid(ar.x + br0 + RIt[(size_t)ch * 4096 + pix]);
            float r1 = fast_sigmoid(ar.y + br1 + RIt[(size_t)(ch + 1) * 4096 + pix]);
            float h0 = g_H[idx0];
            float h1 = g_H[idx1];
            g_U [idx0] = u0;  g_U [idx1] = u1;
            g_HR[idx0] = h0 * r0;  g_HR[idx1] = h1 * r1;
        }
    }
}

// ---------------------------------------------------------------------------
// Phase B: cand = tanh(OI + conv_oh(h*r)); h = h + u*(cand - h); write out.
// ---------------------------------------------------------------------------
#define SMEM_B ((4*66*32 + WSZ + 32) * 4)

__global__ void __launch_bounds__(256, 2)
phaseB_kernel(int t, const float* __restrict__ b_oh, float* __restrict__ out) {
    extern __shared__ float smem[];
    float* sIn = smem;               // 8448
    float* sW  = smem + 8448;        // 9216
    float* sB  = sW + WSZ;

    const int b   = blockIdx.y;
    const int y0  = blockIdx.x * 2;
    const int tid = threadIdx.x;

    for (int i = tid; i < WSZ; i += 256) sW[i] = g_Wt[5 * WSZ + i];
    if (tid < 32) sB[tid] = b_oh[tid];

    const float* hb = g_HR + (size_t)b * RV * HWV;
    for (int i = tid; i < 4 * 66 * 32; i += 256) {
        int cin = i / 264;
        int rem = i - cin * 264;
        int rr  = rem / 66;
        int cc  = rem - rr * 66;
        int gy  = y0 - 1 + rr;
        int gx  = cc - 1;
        float v = 0.0f;
        if ((unsigned)gy < 64u && (unsigned)gx < 64u)
            v = hb[cin * HWV + gy * 64 + gx];
        sIn[cin * 264 + rr * 66 + cc] = v;
    }
    __syncthreads();

    const int col = tid & 63;
    const int c0  = (tid >> 6) * 8;

    u64 acc[2][4];
#pragma unroll
    for (int r = 0; r < 2; ++r)
#pragma unroll
        for (int p = 0; p < 4; ++p) acc[r][p] = 0ULL;

    for (int cin = 0; cin < 32; ++cin) {
        const float* inC = sIn + cin * 264 + col;
        const ulonglong2* wC = (const ulonglong2*)(sW + cin * 288 + c0);
#pragma unroll
        for (int kx = 0; kx < 3; ++kx) {
            u64 vv[4];
#pragma unroll
            for (int rr = 0; rr < 4; ++rr) vv[rr] = pack2(inC[rr * 66 + kx]);
#pragma unroll
            for (int ky = 0; ky < 3; ++ky) {
                ulonglong2 w0 = wC[(ky * 3 + kx) * 8];
                ulonglong2 w1 = wC[(ky * 3 + kx) * 8 + 1];
#pragma unroll
                for (int r = 0; r < 2; ++r) {
                    u64 v = vv[r + ky];
                    ffma2(acc[r][0], v, w0.x);
                    ffma2(acc[r][1], v, w0.y);
                    ffma2(acc[r][2], v, w1.x);
                    ffma2(acc[r][3], v, w1.y);
                }
            }
        }
    }

    const size_t fbase = ((size_t)t * BV + b) * 32 * 4096;
    const float* OIt = g_OI + fbase;
#pragma unroll
    for (int p = 0; p < 4; ++p) {
        int ch = c0 + 2 * p;
        float b0 = sB[ch], b1 = sB[ch + 1];
#pragma unroll
        for (int r = 0; r < 2; ++r) {
            float2 a = unpack2(acc[r][p]);
            int pix  = (y0 + r) * 64 + col;
            int idx0 = (b * 32 + ch) * 4096 + pix;
            int idx1 = idx0 + 4096;
            float cand0 = fast_tanh(a.x + b0 + OIt[(size_t)ch * 4096 + pix]);
            float cand1 = fast_tanh(a.y + b1 + OIt[(size_t)(ch + 1) * 4096 + pix]);
            float u0 = g_U[idx0], u1 = g_U[idx1];
            float h0 = g_H[idx0], h1 = g_H[idx1];
            float hn0 = h0 + u0 * (cand0 - h0);
            float hn1 = h1 + u1 * (cand1 - h1);
            g_H[idx0] = hn0;
            g_H[idx1] = hn1;
            out[((size_t)(b * 32 + ch) * TV + t) * HWV + pix]       = hn0;
            out[((size_t)(b * 32 + ch + 1) * TV + t) * HWV + pix]   = hn1;
        }
    }
}

// ---------------------------------------------------------------------------
// Launch
// ---------------------------------------------------------------------------
extern "C" void kernel_launch(void* const* d_in, const int* in_sizes, int n_in,
                              void* d_out, int out_size) {
    const float* x    = (const float*)d_in[0];
    const float* w_ri = (const float*)d_in[1];
    const float* b_ri = (const float*)d_in[2];
    const float* w_rh = (const float*)d_in[3];
    const float* b_rh = (const float*)d_in[4];
    const float* w_ui = (const float*)d_in[5];
    const float* b_ui = (const float*)d_in[6];
    const float* w_uh = (const float*)d_in[7];
    const float* b_uh = (const float*)d_in[8];
    const float* w_oi = (const float*)d_in[9];
    const float* b_oi = (const float*)d_in[10];
    const float* w_oh = (const float*)d_in[11];
    const float* b_oh = (const float*)d_in[12];
    float* out = (float*)d_out;

    cudaFuncSetAttribute((const void*)conv_in_kernel,
                         cudaFuncAttributeMaxDynamicSharedMemorySize, SMEM_PC);
    cudaFuncSetAttribute((const void*)phaseA_kernel,
                         cudaFuncAttributeMaxDynamicSharedMemorySize, SMEM_A);
    cudaFuncSetAttribute((const void*)phaseB_kernel,
                         cudaFuncAttributeMaxDynamicSharedMemorySize, SMEM_B);

    wtrans_kernel<<<6, 256>>>(w_ui, w_ri, w_oi, w_uh, w_rh, w_oh);
    zeroH_kernel<<<1024, 256>>>();

    conv_in_kernel<<<dim3(16, BV * TV, 3), 256, SMEM_PC>>>(x, b_ui, b_ri, b_oi);

    for (int t = 0; t < TV; ++t) {
        phaseA_kernel<<<dim3(32, BV), 256, SMEM_A>>>(t, b_uh, b_rh);
        phaseB_kernel<<<dim3(32, BV), 256, SMEM_B>>>(t, b_oh, out);
    }
}